// round 17
// baseline (speedup 1.0000x reference)
#include <cuda_runtime.h>
#include <cuda_fp16.h>
#include <mma.h>
#include <math.h>
#include <stdint.h>

using namespace nvcuda;

#define D_MODEL 1024
#define HEADS   16
#define DKH     64
#define D_FF    4096
#define BATCH   2
#define SEQ     2048
#define MROWS   (BATCH * SEQ)   // 4096
#define EPS_LN  1e-6f
#define NELEM   (MROWS * D_MODEL)
#define WELEM   (D_MODEL * D_MODEL)
#define FELEM   (D_FF * D_MODEL)
#define FFELEM  (MROWS * D_FF)

// ---------------- scratch (static device globals; no allocs) ----------------
__device__ __half g_xh[NELEM];
__device__ __half g_wqh[WELEM], g_wkh[WELEM];
__device__ __half g_wvh[WELEM], g_woh[WELEM];
__device__ __half g_w1h[FELEM], g_w2h[FELEM];
__device__ __half g_qh[NELEM], g_kh[NELEM], g_vh[NELEM];
__device__ __half g_ah[NELEM];
__device__ __half g_r1h[NELEM];
__device__ __half g_ffh[FFELEM];
__device__ float g_tmp[NELEM];
__device__ float g_r1f[NELEM];
__device__ float g_tmp2[NELEM];

// ================= helpers ===================================================
#define CP16(dst, src) \
    asm volatile("cp.async.cg.shared.global [%0], [%1], 16;" :: \
        "r"((uint32_t)__cvta_generic_to_shared(dst)), "l"(src))
#define CP_COMMIT() asm volatile("cp.async.commit_group;" ::: "memory")
#define CP_WAIT(n)  asm volatile("cp.async.wait_group %0;" :: "n"(n) : "memory")

#define LDSM4(r0, r1, r2, r3, addr) \
    asm volatile("ldmatrix.sync.aligned.m8n8.x4.shared.b16 {%0,%1,%2,%3}, [%4];" \
        : "=r"(r0), "=r"(r1), "=r"(r2), "=r"(r3) : "r"(addr))
#define LDSM4T(r0, r1, r2, r3, addr) \
    asm volatile("ldmatrix.sync.aligned.m8n8.x4.trans.shared.b16 {%0,%1,%2,%3}, [%4];" \
        : "=r"(r0), "=r"(r1), "=r"(r2), "=r"(r3) : "r"(addr))
#define MMA16816(d0, d1, d2, d3, a0, a1, a2, a3, b0, b1) \
    asm volatile("mma.sync.aligned.m16n8k16.row.col.f32.f16.f16.f32 " \
        "{%0,%1,%2,%3}, {%4,%5,%6,%7}, {%8,%9}, {%0,%1,%2,%3};" \
        : "+f"(d0), "+f"(d1), "+f"(d2), "+f"(d3) \
        : "r"(a0), "r"(a1), "r"(a2), "r"(a3), "r"(b0), "r"(b1))

// ---------------- fused fp32 -> fp16 conversion (all tensors, 1 launch) ------
#define X4  (NELEM / 4)     // 1048576
#define W4  (WELEM / 4)     // 262144
#define F4  (FELEM / 4)     // 1048576
#define CVT_TOTAL (X4 + 4 * W4 + 2 * F4)   // 4194304

__global__ __launch_bounds__(256)
void cvt_all(const float* __restrict__ x,  __half* __restrict__ xh,
             const float* __restrict__ wq, __half* __restrict__ wqh,
             const float* __restrict__ wk, __half* __restrict__ wkh,
             const float* __restrict__ wv, __half* __restrict__ wvh,
             const float* __restrict__ wo, __half* __restrict__ woh,
             const float* __restrict__ w1, __half* __restrict__ w1h,
             const float* __restrict__ w2, __half* __restrict__ w2h)
{
    int i = blockIdx.x * 256 + threadIdx.x;
    if (i >= CVT_TOTAL) return;
    const float* src;
    __half* dst;
    int li = i;
    if (li < X4)                 { src = x;  dst = xh; }
    else if ((li -= X4) < W4)    { src = wq; dst = wqh; }
    else if ((li -= W4) < W4)    { src = wk; dst = wkh; }
    else if ((li -= W4) < W4)    { src = wv; dst = wvh; }
    else if ((li -= W4) < W4)    { src = wo; dst = woh; }
    else if ((li -= W4) < F4)    { src = w1; dst = w1h; }
    else { li -= F4;               src = w2; dst = w2h; }
    float4 v = ((const float4*)src)[li];
    __half2 h01 = __floats2half2_rn(v.x, v.y);
    __half2 h23 = __floats2half2_rn(v.z, v.w);
    ((uint2*)dst)[li] = make_uint2(*(uint32_t*)&h01, *(uint32_t*)&h23);
}

// ================= fp16 GEMM: C = A @ B^T (+epilogue), single pass ===========
// block 128x128, 8 warps (4m x 2n), warp tile 32x64, k-chunk 32, 2 stages.
// EPI: 0 none, 1 relu, 2 residual. OUT: 0 fp32, 2 fp16. QKV fused. MINB=occ.
#define GLDT    40
#define GTILE   (128 * GLDT)
#define GSTAGE  (2 * GTILE)
#define GEMM_SMEM 40960                      // 2 stages; epilogue stages 64 rows

__device__ __forceinline__ void gemm_issue(__half* st,
    const __half* Ahg, const __half* Bhg, int K, int k0, int tid)
{
    __half* sAh = st;
    __half* sBh = st + GTILE;
#pragma unroll
    for (int it = 0; it < 2; it++) {
        int ch = tid + it * 256;
        int r = ch >> 2;
        int c = (ch & 3) * 8;
        CP16(sAh + r * GLDT + c, Ahg + (size_t)r * K + k0 + c);
        CP16(sBh + r * GLDT + c, Bhg + (size_t)r * K + k0 + c);
    }
}

template <int EPI, int OUT, int QKV, int MINB>
__global__ __launch_bounds__(256, MINB)
void gemm_fp16(const __half* __restrict__ Ah,
               const __half* __restrict__ Bh1, const __half* __restrict__ Bh2,
               const __half* __restrict__ Bh3,
               const float* __restrict__ Rf, float* __restrict__ Cf,
               __half* __restrict__ Hh1, __half* __restrict__ Hh2,
               __half* __restrict__ Hh3,
               int M, int N, int K)
{
    extern __shared__ __half sh[];

    const int tid = threadIdx.x;
    const int wid = tid >> 5;
    const int wm = (wid & 3) * 32;
    const int wn = (wid >> 2) * 64;

    const __half* Bh = Bh1;
    __half* Hh = Hh1;
    int col0;
    float oscale = 1.f;
    if (QKV) {
        const int mat = blockIdx.x >> 3;
        col0 = (blockIdx.x & 7) * 128;
        if (mat == 1) { Bh = Bh2; Hh = Hh2; }
        else if (mat == 2) { Bh = Bh3; Hh = Hh3; }
        else oscale = 0.125f;                 // fold 1/sqrt(dk) into Q
    } else {
        col0 = blockIdx.x * 128;
    }
    const int row0 = blockIdx.y * 128;
    const __half* Ahg = Ah + (size_t)row0 * K;
    const __half* Bhg = Bh + (size_t)col0 * K;

    wmma::fragment<wmma::accumulator, 16, 16, 16, float> acc[2][4];
#pragma unroll
    for (int i = 0; i < 2; i++)
#pragma unroll
        for (int j = 0; j < 4; j++) wmma::fill_fragment(acc[i][j], 0.f);

    const int T = K / 32;
    gemm_issue(sh, Ahg, Bhg, K, 0, tid);
    CP_COMMIT();

    for (int t = 0; t < T; t++) {
        CP_WAIT(0);
        __syncthreads();
        if (t + 1 < T) {
            gemm_issue(sh + ((t + 1) & 1) * GSTAGE, Ahg, Bhg, K, (t + 1) * 32, tid);
            CP_COMMIT();
        }
        __half* Ahs = sh + (t & 1) * GSTAGE;
        __half* Bhs = Ahs + GTILE;
#pragma unroll
        for (int ks = 0; ks < 32; ks += 16) {
            wmma::fragment<wmma::matrix_a, 16, 16, 16, __half, wmma::row_major> a_hi[2];
#pragma unroll
            for (int i = 0; i < 2; i++)
                wmma::load_matrix_sync(a_hi[i], Ahs + (wm + i * 16) * GLDT + ks, GLDT);
#pragma unroll
            for (int j = 0; j < 4; j++) {
                wmma::fragment<wmma::matrix_b, 16, 16, 16, __half, wmma::col_major> b_hi;
                wmma::load_matrix_sync(b_hi, Bhs + (wn + j * 16) * GLDT + ks, GLDT);
#pragma unroll
                for (int i = 0; i < 2; i++)
                    wmma::mma_sync(acc[i][j], a_hi[i], b_hi, acc[i][j]);
            }
        }
        __syncthreads();
    }

    if (OUT == 0) {
#pragma unroll
        for (int i = 0; i < 2; i++) {
#pragma unroll
            for (int j = 0; j < 4; j++) {
                const int row = row0 + wm + i * 16;
                const int col = col0 + wn + j * 16;
                if (EPI == 2) {
                    wmma::fragment<wmma::accumulator, 16, 16, 16, float> rf;
                    wmma::load_matrix_sync(rf, Rf + (size_t)row * N + col, N, wmma::mem_row_major);
#pragma unroll
                    for (int e = 0; e < rf.num_elements; e++) acc[i][j].x[e] += rf.x[e];
                }
                if (EPI == 1) {
#pragma unroll
                    for (int e = 0; e < acc[i][j].num_elements; e++)
                        acc[i][j].x[e] = fmaxf(acc[i][j].x[e], 0.f);
                }
                wmma::store_matrix_sync(Cf + (size_t)row * N + col, acc[i][j], N, wmma::mem_row_major);
            }
        }
    } else {
        // fp16 out: stage 64 rows at a time in smem (fits 40KB), then convert
        float* stg = (float*)sh;              // 64 x 132 fp32 = 33792 B
#pragma unroll
        for (int gg = 0; gg < 2; gg++) {
            __syncthreads();
            if ((wm >> 6) == gg) {
                const int wmloc = wm & 63;
#pragma unroll
                for (int i = 0; i < 2; i++) {
#pragma unroll
                    for (int j = 0; j < 4; j++) {
                        if (EPI == 1) {
#pragma unroll
                            for (int e = 0; e < acc[i][j].num_elements; e++)
                                acc[i][j].x[e] = fmaxf(acc[i][j].x[e], 0.f);
                        }
                        wmma::store_matrix_sync(stg + (wmloc + i * 16) * 132 + wn + j * 16,
                                                acc[i][j], 132, wmma::mem_row_major);
                    }
                }
            }
            __syncthreads();
            const int r = tid >> 2;           // 0..63
            const int cb = (tid & 3) * 32;
#pragma unroll
            for (int j = 0; j < 32; j += 4) {
                float4 v = *(const float4*)(stg + r * 132 + cb + j);
                v.x *= oscale; v.y *= oscale; v.z *= oscale; v.w *= oscale;
                __half2 h01 = __floats2half2_rn(v.x, v.y);
                __half2 h23 = __floats2half2_rn(v.z, v.w);
                const size_t off = (size_t)(row0 + gg * 64 + r) * N + col0 + cb + j;
                *(uint2*)(Hh + off) = make_uint2(*(uint32_t*)&h01, *(uint32_t*)&h23);
            }
        }
    }
}

// ================= register-resident flash attention (mma.sync) ==============
// Q pre-scaled by 1/sqrt(dk). 256 threads = 8 warps; warp owns 16 q-rows.
#define FLDH 72
#define FK_OFF (128 * FLDH)               // halfs
#define FV_OFF (FK_OFF + 2 * 64 * FLDH)
#define FA_SMEM ((128 * FLDH + 4 * 64 * FLDH) * 2)   // 55296 B

__global__ __launch_bounds__(256, 2)
void flash_reg(const __half* __restrict__ Qg, const __half* __restrict__ Kg,
               const __half* __restrict__ Vg, __half* __restrict__ Og)
{
    extern __shared__ __half fs[];
    __half* Qs = fs;

    const int qb = gridDim.x - 1 - blockIdx.x;   // heavy q-blocks first
    const int h = blockIdx.y, bb = blockIdx.z;
    const int tid = threadIdx.x;
    const int wid = tid >> 5, lane = tid & 31;
    const int g = lane >> 2, tg = lane & 3;
    const int band = wid * 16;
    const int q0 = qb * 128;
    const size_t base = (size_t)bb * SEQ * D_MODEL + (size_t)h * DKH;

#pragma unroll
    for (int it = 0; it < 4; it++) {
        int ch = tid + it * 256;
        int r = ch >> 3, c = (ch & 7) * 8;
        CP16(Qs + r * FLDH + c, Qg + base + (size_t)(q0 + r) * D_MODEL + c);
    }
#pragma unroll
    for (int it = 0; it < 2; it++) {
        int ch = tid + it * 256;
        int r = ch >> 3, c = (ch & 7) * 8;
        CP16(fs + FK_OFF + r * FLDH + c, Kg + base + (size_t)r * D_MODEL + c);
        CP16(fs + FV_OFF + r * FLDH + c, Vg + base + (size_t)r * D_MODEL + c);
    }
    CP_COMMIT();
    CP_WAIT(0);
    __syncthreads();

    uint32_t qa[4][4];
    {
        const uint32_t qb32 = (uint32_t)__cvta_generic_to_shared(Qs);
        const int i = lane & 7, seg = lane >> 3;
        const int rr = band + i + ((seg & 1) ? 8 : 0);
        const int cc = (seg & 2) ? 8 : 0;
#pragma unroll
        for (int ks = 0; ks < 4; ks++) {
            uint32_t addr = qb32 + (uint32_t)((rr * FLDH + ks * 16 + cc) * 2);
            LDSM4(qa[ks][0], qa[ks][1], qa[ks][2], qa[ks][3], addr);
        }
    }

    float m0 = -1e30f, m1 = -1e30f, l0 = 0.f, l1 = 0.f;
    float o[8][4];
#pragma unroll
    for (int dt = 0; dt < 8; dt++)
#pragma unroll
        for (int e = 0; e < 4; e++) o[dt][e] = 0.f;

    const int kmax = 2 * qb + 1;
    for (int kb = 0; kb <= kmax; kb++) {
        const int cur = kb & 1;
        if (kb + 1 <= kmax) {
            const int nxt = cur ^ 1;
            const int k0n = (kb + 1) * 64;
#pragma unroll
            for (int it = 0; it < 2; it++) {
                int ch = tid + it * 256;
                int r = ch >> 3, c = (ch & 7) * 8;
                CP16(fs + FK_OFF + nxt * 64 * FLDH + r * FLDH + c,
                     Kg + base + (size_t)(k0n + r) * D_MODEL + c);
                CP16(fs + FV_OFF + nxt * 64 * FLDH + r * FLDH + c,
                     Vg + base + (size_t)(k0n + r) * D_MODEL + c);
            }
            CP_COMMIT();
        }
        const int k0 = kb * 64;

        float s[8][4];
#pragma unroll
        for (int nt = 0; nt < 8; nt++)
#pragma unroll
            for (int e = 0; e < 4; e++) s[nt][e] = 0.f;
        {
            const uint32_t kb32 = (uint32_t)__cvta_generic_to_shared(fs + FK_OFF + cur * 64 * FLDH);
            const int i = lane & 7, seg = lane >> 3;
            const int rr = i + ((seg & 2) ? 8 : 0);
            const int cc = (seg & 1) ? 8 : 0;
#pragma unroll
            for (int ks = 0; ks < 4; ks++) {
#pragma unroll
                for (int p = 0; p < 4; p++) {
                    uint32_t b0, b1, b2, b3;
                    uint32_t addr = kb32 + (uint32_t)(((p * 16 + rr) * FLDH + ks * 16 + cc) * 2);
                    LDSM4(b0, b1, b2, b3, addr);
                    MMA16816(s[2 * p][0], s[2 * p][1], s[2 * p][2], s[2 * p][3],
                             qa[ks][0], qa[ks][1], qa[ks][2], qa[ks][3], b0, b1);
                    MMA16816(s[2 * p + 1][0], s[2 * p + 1][1], s[2 * p + 1][2], s[2 * p + 1][3],
                             qa[ks][0], qa[ks][1], qa[ks][2], qa[ks][3], b2, b3);
                }
            }
        }

        uint32_t pa[4][4];
        {
            const bool needmask = (kb >= 2 * qb);
            const int row0 = q0 + band + g;
            const int row1 = row0 + 8;
            float mx0 = -1e30f, mx1 = -1e30f;
#pragma unroll
            for (int nt = 0; nt < 8; nt++) {
                float v0 = s[nt][0], v1 = s[nt][1];
                float v2 = s[nt][2], v3 = s[nt][3];
                if (needmask) {
                    const int col = k0 + nt * 8 + 2 * tg;
                    if (col > row0)     v0 = -1e30f;
                    if (col + 1 > row0) v1 = -1e30f;
                    if (col > row1)     v2 = -1e30f;
                    if (col + 1 > row1) v3 = -1e30f;
                }
                s[nt][0] = v0; s[nt][1] = v1; s[nt][2] = v2; s[nt][3] = v3;
                mx0 = fmaxf(mx0, fmaxf(v0, v1));
                mx1 = fmaxf(mx1, fmaxf(v2, v3));
            }
            mx0 = fmaxf(mx0, __shfl_xor_sync(0xFFFFFFFFu, mx0, 1));
            mx0 = fmaxf(mx0, __shfl_xor_sync(0xFFFFFFFFu, mx0, 2));
            mx1 = fmaxf(mx1, __shfl_xor_sync(0xFFFFFFFFu, mx1, 1));
            mx1 = fmaxf(mx1, __shfl_xor_sync(0xFFFFFFFFu, mx1, 2));
            const float mn0 = fmaxf(m0, mx0), mn1 = fmaxf(m1, mx1);
            const float corr0 = __expf(m0 - mn0), corr1 = __expf(m1 - mn1);
            float ls0 = 0.f, ls1 = 0.f;
#pragma unroll
            for (int nt = 0; nt < 8; nt++) {
                float p0 = __expf(s[nt][0] - mn0), p1 = __expf(s[nt][1] - mn0);
                float p2 = __expf(s[nt][2] - mn1), p3 = __expf(s[nt][3] - mn1);
                ls0 += p0 + p1;
                ls1 += p2 + p3;
                __half2 h01 = __floats2half2_rn(p0, p1);
                __half2 h23 = __floats2half2_rn(p2, p3);
                pa[nt >> 1][(nt & 1) ? 2 : 0] = *(uint32_t*)&h01;
                pa[nt >> 1][(nt & 1) ? 3 : 1] = *(uint32_t*)&h23;
            }
            ls0 += __shfl_xor_sync(0xFFFFFFFFu, ls0, 1);
            ls0 += __shfl_xor_sync(0xFFFFFFFFu, ls0, 2);
            ls1 += __shfl_xor_sync(0xFFFFFFFFu, ls1, 1);
            ls1 += __shfl_xor_sync(0xFFFFFFFFu, ls1, 2);
            l0 = l0 * corr0 + ls0;
            l1 = l1 * corr1 + ls1;
            m0 = mn0; m1 = mn1;
#pragma unroll
            for (int dt = 0; dt < 8; dt++) {
                o[dt][0] *= corr0; o[dt][1] *= corr0;
                o[dt][2] *= corr1; o[dt][3] *= corr1;
            }
        }

        {
            const uint32_t vb32 = (uint32_t)__cvta_generic_to_shared(fs + FV_OFF + cur * 64 * FLDH);
            const int i = lane & 7, seg = lane >> 3;
            const int rr = i + ((seg & 1) ? 8 : 0);
            const int cc = (seg & 2) ? 8 : 0;
#pragma unroll
            for (int jp = 0; jp < 4; jp++) {
#pragma unroll
                for (int p = 0; p < 4; p++) {
                    uint32_t b0, b1, b2, b3;
                    uint32_t addr = vb32 + (uint32_t)(((jp * 16 + rr) * FLDH + p * 16 + cc) * 2);
                    LDSM4T(b0, b1, b2, b3, addr);
                    MMA16816(o[2 * p][0], o[2 * p][1], o[2 * p][2], o[2 * p][3],
                             pa[jp][0], pa[jp][1], pa[jp][2], pa[jp][3], b0, b1);
                    MMA16816(o[2 * p + 1][0], o[2 * p + 1][1], o[2 * p + 1][2], o[2 * p + 1][3],
                             pa[jp][0], pa[jp][1], pa[jp][2], pa[jp][3], b2, b3);
                }
            }
        }

        if (kb + 1 <= kmax) {
            CP_WAIT(0);
            __syncthreads();
        }
    }

    {
        const float inv0 = 1.f / l0, inv1 = 1.f / l1;
        const int row0 = q0 + band + g;
#pragma unroll
        for (int dt = 0; dt < 8; dt++) {
            __half2 h0 = __floats2half2_rn(o[dt][0] * inv0, o[dt][1] * inv0);
            __half2 h1 = __floats2half2_rn(o[dt][2] * inv1, o[dt][3] * inv1);
            *(uint32_t*)(Og + base + (size_t)row0 * D_MODEL + dt * 8 + 2 * tg) = *(uint32_t*)&h0;
            *(uint32_t*)(Og + base + (size_t)(row0 + 8) * D_MODEL + dt * 8 + 2 * tg) = *(uint32_t*)&h1;
        }
    }
}

// ---------------- LayerNorm (ddof=1), optional fp16 output -------------------
template <bool HL>
__global__ __launch_bounds__(256)
void layernorm_k(const float* __restrict__ in, const float* __restrict__ gamma,
                 const float* __restrict__ beta, float* __restrict__ out,
                 __half* __restrict__ oh)
{
    const int row = blockIdx.x;
    const int tid = threadIdx.x;
    const float4 v = ((const float4*)(in + (size_t)row * D_MODEL))[tid];
    float s  = v.x + v.y + v.z + v.w;
    float ss = v.x * v.x + v.y * v.y + v.z * v.z + v.w * v.w;

    __shared__ float rs[8], rss[8];
#pragma unroll
    for (int o = 16; o > 0; o >>= 1) {
        s  += __shfl_down_sync(0xFFFFFFFFu, s, o);
        ss += __shfl_down_sync(0xFFFFFFFFu, ss, o);
    }
    if ((tid & 31) == 0) { rs[tid >> 5] = s; rss[tid >> 5] = ss; }
    __syncthreads();
    float S = 0.f, SS = 0.f;
#pragma unroll
    for (int i = 0; i < 8; i++) { S += rs[i]; SS += rss[i]; }

    const float mean = S * (1.f / (float)D_MODEL);
    const float var  = (SS - (float)D_MODEL * mean * mean) * (1.f / (float)(D_MODEL - 1));
    const float inv  = rsqrtf(var + EPS_LN);

    const float4 g = ((const float4*)gamma)[tid];
    const float4 b = ((const float4*)beta)[tid];
    float4 o;
    o.x = g.x * (v.x - mean) * inv + b.x;
    o.y = g.y * (v.y - mean) * inv + b.y;
    o.z = g.z * (v.z - mean) * inv + b.z;
    o.w = g.w * (v.w - mean) * inv + b.w;
    ((float4*)(out + (size_t)row * D_MODEL))[tid] = o;
    if (HL) {
        __half2 h01 = __floats2half2_rn(o.x, o.y);
        __half2 h23 = __floats2half2_rn(o.z, o.w);
        ((uint2*)(oh + (size_t)row * D_MODEL))[tid] =
            make_uint2(*(uint32_t*)&h01, *(uint32_t*)&h23);
    }
}

// ---------------- host launcher ---------------------------------------------
extern "C" void kernel_launch(void* const* d_in, const int* in_sizes, int n_in,
                              void* d_out, int out_size)
{
    (void)in_sizes; (void)n_in; (void)out_size;
    const float* x  = (const float*)d_in[0];
    const float* Wq = (const float*)d_in[2];
    const float* Wk = (const float*)d_in[3];
    const float* Wv = (const float*)d_in[4];
    const float* Wo = (const float*)d_in[5];
    const float* W1 = (const float*)d_in[6];
    const float* W2 = (const float*)d_in[7];
    const float* g1 = (const float*)d_in[8];
    const float* b1 = (const float*)d_in[9];
    const float* g2 = (const float*)d_in[10];
    const float* b2 = (const float*)d_in[11];
    float* out = (float*)d_out;

    __half *xh, *wqh, *wkh, *wvh, *woh, *w1h, *w2h;
    __half *qh, *kh, *vh, *ah, *r1h, *ffh;
    float *tmp, *r1f, *tmp2;
    cudaGetSymbolAddress((void**)&xh, g_xh);
    cudaGetSymbolAddress((void**)&wqh, g_wqh); cudaGetSymbolAddress((void**)&wkh, g_wkh);
    cudaGetSymbolAddress((void**)&wvh, g_wvh); cudaGetSymbolAddress((void**)&woh, g_woh);
    cudaGetSymbolAddress((void**)&w1h, g_w1h); cudaGetSymbolAddress((void**)&w2h, g_w2h);
    cudaGetSymbolAddress((void**)&qh, g_qh);   cudaGetSymbolAddress((void**)&kh, g_kh);
    cudaGetSymbolAddress((void**)&vh, g_vh);   cudaGetSymbolAddress((void**)&ah, g_ah);
    cudaGetSymbolAddress((void**)&r1h, g_r1h); cudaGetSymbolAddress((void**)&ffh, g_ffh);
    cudaGetSymbolAddress((void**)&tmp, g_tmp);
    cudaGetSymbolAddress((void**)&r1f, g_r1f);
    cudaGetSymbolAddress((void**)&tmp2, g_tmp2);

    cudaFuncSetAttribute(gemm_fp16<0,2,1,3>, cudaFuncAttributeMaxDynamicSharedMemorySize, GEMM_SMEM);
    cudaFuncSetAttribute(gemm_fp16<1,2,0,3>, cudaFuncAttributeMaxDynamicSharedMemorySize, GEMM_SMEM);
    cudaFuncSetAttribute(gemm_fp16<2,0,0,2>, cudaFuncAttributeMaxDynamicSharedMemorySize, GEMM_SMEM);
    cudaFuncSetAttribute(flash_reg, cudaFuncAttributeMaxDynamicSharedMemorySize, FA_SMEM);

    const dim3 blk(256);

    // ---- fused conversion pass (1 launch) ----
    cvt_all<<<CVT_TOTAL / 256, blk>>>(x, xh, Wq, wqh, Wk, wkh, Wv, wvh,
                                      Wo, woh, W1, w1h, W2, w2h);

    const dim3 gQKV(24, MROWS / 128);
    const dim3 gD(D_MODEL / 128, MROWS / 128);
    const dim3 gF(D_FF / 128, MROWS / 128);

    // Fused QKV projection -> fp16 (Q pre-scaled by 1/8); occ 3
    gemm_fp16<0,2,1,3><<<gQKV, blk, GEMM_SMEM>>>(xh, wqh, wkh, wvh,
                                                 nullptr, nullptr,
                                                 qh, kh, vh,
                                                 MROWS, D_MODEL, D_MODEL);

    // Register-resident flash attention
    flash_reg<<<dim3(SEQ / 128, HEADS, BATCH), blk, FA_SMEM>>>(qh, kh, vh, ah);

    // Output projection + residual x -> fp32, then LN1 (fp32 + fp16)
    gemm_fp16<2,0,0,2><<<gD, blk, GEMM_SMEM>>>(ah, woh, nullptr, nullptr,
                                               x, tmp,
                                               nullptr, nullptr, nullptr,
                                               MROWS, D_MODEL, D_MODEL);
    layernorm_k<true><<<MROWS, blk>>>(tmp, g1, b1, r1f, r1h);

    // FFN; W1 GEMM at occ 3 (multi-wave)
    gemm_fp16<1,2,0,3><<<gF, blk, GEMM_SMEM>>>(r1h, w1h, nullptr, nullptr,
                                               nullptr, nullptr,
                                               ffh, nullptr, nullptr,
                                               MROWS, D_FF, D_MODEL);
    gemm_fp16<2,0,0,2><<<gD, blk, GEMM_SMEM>>>(ffh, w2h, nullptr, nullptr,
                                               r1f, tmp2,
                                               nullptr, nullptr, nullptr,
                                               MROWS, D_MODEL, D_FF);
    layernorm_k<false><<<MROWS, blk>>>(tmp2, g2, b2, out, nullptr);
}